// round 7
// baseline (speedup 1.0000x reference)
#include <cuda_runtime.h>
#include <cuda_fp16.h>
#include <cstdint>

#define N_NODES 50000
#define D_IN 128
#define D_OUT 64
#define N_ETYPES 3
#define E_PER_ETYPE 500000
#define P_ETYPE 0.5f
#define CAP 96   // max in-degree per (etype,node); Poisson(10) tail => never hit

// Scratch (no device mallocs allowed).
__device__ int   g_cnt[N_ETYPES * N_NODES];                     // 0.6 MB
__device__ int   g_bins[(size_t)N_ETYPES * N_NODES * CAP];      // 57.6 MB
__device__ uint2 g_feat16[(size_t)N_NODES * (D_IN / 4)];        // 12.8 MB (4 halves per uint2)
__device__ uint2 g_h16[(size_t)N_NODES * (D_IN / 4)];           // 12.8 MB

__device__ __forceinline__ float tanh_fast(float x) {
    float y;
    asm("tanh.approx.f32 %0, %1;" : "=f"(y) : "f"(x));
    return y;
}

__device__ __forceinline__ uint2 pack4(float a, float b, float c, float d) {
    __half2 lo = __floats2half2_rn(a, b);
    __half2 hi = __floats2half2_rn(c, d);
    uint2 u;
    u.x = *reinterpret_cast<unsigned*>(&lo);
    u.y = *reinterpret_cast<unsigned*>(&hi);
    return u;
}

__device__ __forceinline__ float4 unpack4(uint2 u) {
    __half2 lo = *reinterpret_cast<__half2*>(&u.x);
    __half2 hi = *reinterpret_cast<__half2*>(&u.y);
    float2 a = __half22float2(lo);
    float2 c = __half22float2(hi);
    return make_float4(a.x, a.y, c.x, c.y);
}

// Convert feat fp32 -> fp16 cache; first threads also zero g_cnt
// (replaces the separate memset launch; bin_kernel runs after us).
__global__ void __launch_bounds__(256) convert_kernel(const float* __restrict__ feat)
{
    const int i = blockIdx.x * blockDim.x + threadIdx.x;
    if (i < N_ETYPES * N_NODES) g_cnt[i] = 0;
    if (i >= N_NODES * (D_IN / 4)) return;
    const float4 v = reinterpret_cast<const float4*>(feat)[i];
    g_feat16[i] = pack4(v.x, v.y, v.z, v.w);
}

// Pass 1: bin edges by (etype, dst). 4 edges per thread -> 4 independent chains.
__global__ void __launch_bounds__(256) bin_kernel(const int* __restrict__ edge_index)
{
    const int t = blockIdx.x * blockDim.x + threadIdx.x;
    if (t >= N_ETYPES * (E_PER_ETYPE / 4)) return;
    const int e    = t / (E_PER_ETYPE / 4);
    const int idx4 = (t - e * (E_PER_ETYPE / 4)) * 4;

    const int* base = edge_index + (size_t)e * 2 * E_PER_ETYPE;
    const int4 s = *reinterpret_cast<const int4*>(base + idx4);
    const int4 d = *reinterpret_cast<const int4*>(base + E_PER_ETYPE + idx4);

    const int s0 = atomicAdd(&g_cnt[e * N_NODES + d.x], 1);
    const int s1 = atomicAdd(&g_cnt[e * N_NODES + d.y], 1);
    const int s2 = atomicAdd(&g_cnt[e * N_NODES + d.z], 1);
    const int s3 = atomicAdd(&g_cnt[e * N_NODES + d.w], 1);

    if (s0 < CAP) g_bins[((size_t)e * N_NODES + d.x) * CAP + s0] = s.x;
    if (s1 < CAP) g_bins[((size_t)e * N_NODES + d.y) * CAP + s1] = s.y;
    if (s2 < CAP) g_bins[((size_t)e * N_NODES + d.z) * CAP + s2] = s.z;
    if (s3 < CAP) g_bins[((size_t)e * N_NODES + d.w) * CAP + s3] = s.w;
}

// Pass 2: pull gather-mean (fp16 payload, fp32 accum) + tanh + residual(fp32)
// + tanh -> g_h16. One warp per node; 4 independent gather chains (MLP=4).
__global__ void __launch_bounds__(256) gather_kernel(const float* __restrict__ feat)
{
    const int gw   = (blockIdx.x * blockDim.x + threadIdx.x) >> 5;
    const int lane = threadIdx.x & 31;
    if (gw >= N_NODES) return;
    const int n = gw;

    // Residual path stays exact fp32.
    const float4 f = reinterpret_cast<const float4*>(feat)[(size_t)n * (D_IN / 4) + lane];
    float h0 = f.x, h1 = f.y, h2 = f.z, h3 = f.w;

    #pragma unroll
    for (int e = 0; e < N_ETYPES; e++) {
        const int c = g_cnt[e * N_NODES + n];
        const int* bin = g_bins + ((size_t)e * N_NODES + n) * CAP;
        float4 sa = make_float4(0.f, 0.f, 0.f, 0.f);
        float4 sb = make_float4(0.f, 0.f, 0.f, 0.f);
        float4 sc = make_float4(0.f, 0.f, 0.f, 0.f);
        float4 sd = make_float4(0.f, 0.f, 0.f, 0.f);
        int i = 0;
        for (; i + 4 <= c; i += 4) {           // 4 independent chains -> MLP=4
            const int4 p = *reinterpret_cast<const int4*>(bin + i);  // 16B-aligned
            const float4 va = unpack4(__ldg(&g_feat16[(size_t)p.x * (D_IN / 4) + lane]));
            const float4 vb = unpack4(__ldg(&g_feat16[(size_t)p.y * (D_IN / 4) + lane]));
            const float4 vc = unpack4(__ldg(&g_feat16[(size_t)p.z * (D_IN / 4) + lane]));
            const float4 vd = unpack4(__ldg(&g_feat16[(size_t)p.w * (D_IN / 4) + lane]));
            sa.x += va.x; sa.y += va.y; sa.z += va.z; sa.w += va.w;
            sb.x += vb.x; sb.y += vb.y; sb.z += vb.z; sb.w += vb.w;
            sc.x += vc.x; sc.y += vc.y; sc.z += vc.z; sc.w += vc.w;
            sd.x += vd.x; sd.y += vd.y; sd.z += vd.z; sd.w += vd.w;
        }
        for (; i < c; i++) {
            const float4 va = unpack4(__ldg(&g_feat16[(size_t)bin[i] * (D_IN / 4) + lane]));
            sa.x += va.x; sa.y += va.y; sa.z += va.z; sa.w += va.w;
        }
        const float inv = 1.0f / fmaxf((float)c, 1.0f);
        h0 += P_ETYPE * tanh_fast((sa.x + sb.x + sc.x + sd.x) * inv);
        h1 += P_ETYPE * tanh_fast((sa.y + sb.y + sc.y + sd.y) * inv);
        h2 += P_ETYPE * tanh_fast((sa.z + sb.z + sc.z + sd.z) * inv);
        h3 += P_ETYPE * tanh_fast((sa.w + sb.w + sc.w + sd.w) * inv);
    }

    g_h16[(size_t)n * (D_IN / 4) + lane] =
        pack4(tanh_fast(h0), tanh_fast(h1), tanh_fast(h2), tanh_fast(h3));
}

// Pass 3: out = h @ W + b. Register-blocked, L1-cached, no shared memory.
// Block = 256 threads, 64 nodes. Thread (jg, quad) computes 4 nodes x 4 cols.
// Grid 782 -> 5.3 blocks/SM, smooth tail; ~48 regs -> high occupancy.
__global__ void __launch_bounds__(256) gemm_kernel(
    const float* __restrict__ W,
    const float* __restrict__ b,
    float* __restrict__ out)
{
    const int tid  = threadIdx.x;
    const int jg   = tid & 15;         // cols 4*jg .. 4*jg+3
    const int quad = tid >> 4;         // node quad within 64-node tile
    const int n0   = blockIdx.x * 64 + quad * 4;

    const float4* W4 = reinterpret_cast<const float4*>(W);   // W4[k*16 + jg] = W[k][4jg..4jg+3]

    // Clamped row pointers (OOB threads read node N-1, stores guarded below).
    const uint2* hp[4];
    #pragma unroll
    for (int i = 0; i < 4; i++) {
        int n = n0 + i; if (n > N_NODES - 1) n = N_NODES - 1;
        hp[i] = g_h16 + (size_t)n * (D_IN / 4);
    }

    float acc[4][4];
    #pragma unroll
    for (int i = 0; i < 4; i++)
        #pragma unroll
        for (int j = 0; j < 4; j++) acc[i][j] = 0.f;

    #pragma unroll 4
    for (int k4 = 0; k4 < D_IN / 4; k4++) {
        const float4 wv0 = __ldg(&W4[(k4 * 4 + 0) * 16 + jg]);
        const float4 wv1 = __ldg(&W4[(k4 * 4 + 1) * 16 + jg]);
        const float4 wv2 = __ldg(&W4[(k4 * 4 + 2) * 16 + jg]);
        const float4 wv3 = __ldg(&W4[(k4 * 4 + 3) * 16 + jg]);
        #pragma unroll
        for (int i = 0; i < 4; i++) {
            const float4 hv = unpack4(__ldg(&hp[i][k4]));
            acc[i][0] = fmaf(hv.x, wv0.x, acc[i][0]); acc[i][0] = fmaf(hv.y, wv1.x, acc[i][0]);
            acc[i][0] = fmaf(hv.z, wv2.x, acc[i][0]); acc[i][0] = fmaf(hv.w, wv3.x, acc[i][0]);
            acc[i][1] = fmaf(hv.x, wv0.y, acc[i][1]); acc[i][1] = fmaf(hv.y, wv1.y, acc[i][1]);
            acc[i][1] = fmaf(hv.z, wv2.y, acc[i][1]); acc[i][1] = fmaf(hv.w, wv3.y, acc[i][1]);
            acc[i][2] = fmaf(hv.x, wv0.z, acc[i][2]); acc[i][2] = fmaf(hv.y, wv1.z, acc[i][2]);
            acc[i][2] = fmaf(hv.z, wv2.z, acc[i][2]); acc[i][2] = fmaf(hv.w, wv3.z, acc[i][2]);
            acc[i][3] = fmaf(hv.x, wv0.w, acc[i][3]); acc[i][3] = fmaf(hv.y, wv1.w, acc[i][3]);
            acc[i][3] = fmaf(hv.z, wv2.w, acc[i][3]); acc[i][3] = fmaf(hv.w, wv3.w, acc[i][3]);
        }
    }

    const float4 bias = __ldg(&reinterpret_cast<const float4*>(b)[jg]);
    float4* out4 = reinterpret_cast<float4*>(out);
    #pragma unroll
    for (int i = 0; i < 4; i++) {
        const int n = n0 + i;
        if (n < N_NODES) {
            out4[(size_t)n * (D_OUT / 4) + jg] =
                make_float4(acc[i][0] + bias.x, acc[i][1] + bias.y,
                            acc[i][2] + bias.z, acc[i][3] + bias.w);
        }
    }
}

extern "C" void kernel_launch(void* const* d_in, const int* in_sizes, int n_in,
                              void* d_out, int out_size)
{
    // Identify inputs by unique element counts (robust to metadata ordering).
    const float* feat = nullptr;
    const float* W    = nullptr;
    const float* b    = nullptr;
    const int*   ei   = nullptr;
    for (int i = 0; i < n_in; i++) {
        switch (in_sizes[i]) {
            case 6400000: feat = (const float*)d_in[i]; break;
            case 8192:    W    = (const float*)d_in[i]; break;
            case 64:      b    = (const float*)d_in[i]; break;
            case 3000000: ei   = (const int*)d_in[i];   break;
            default: break;
        }
    }
    float* out = (float*)d_out;

    convert_kernel<<<(N_NODES * (D_IN / 4) + 255) / 256, 256>>>(feat);

    const int groups = N_ETYPES * (E_PER_ETYPE / 4);
    bin_kernel<<<(groups + 255) / 256, 256>>>(ei);

    gather_kernel<<<(N_NODES + 7) / 8, 256>>>(feat);

    gemm_kernel<<<(N_NODES + 63) / 64, 256>>>(W, b, out);
}

// round 9
// speedup vs baseline: 1.2591x; 1.2591x over previous
#include <cuda_runtime.h>
#include <cuda_fp16.h>
#include <cstdint>

#define N_NODES 50000
#define D_IN 128
#define D_OUT 64
#define N_ETYPES 3
#define E_PER_ETYPE 500000
#define P_ETYPE 0.5f
#define CAP 96   // max in-degree per (etype,node); Poisson(10) tail => never hit

// Scratch (no device mallocs allowed).
__device__ int    g_cnt[N_ETYPES * N_NODES];                    // 0.6 MB
__device__ int    g_bins[(size_t)N_ETYPES * N_NODES * CAP];     // 57.6 MB
__device__ uint2  g_feat16[(size_t)N_NODES * (D_IN / 4)];       // 12.8 MB
__device__ uint2  g_h16[(size_t)N_NODES * (D_IN / 4)];          // 12.8 MB
__device__ __half g_Wt16[D_OUT * D_IN];                         // 16 KB, Wt16[j*128+k] = W[k][j]

__device__ __forceinline__ float tanh_fast(float x) {
    float y;
    asm("tanh.approx.f32 %0, %1;" : "=f"(y) : "f"(x));
    return y;
}

__device__ __forceinline__ uint2 pack4(float a, float b, float c, float d) {
    __half2 lo = __floats2half2_rn(a, b);
    __half2 hi = __floats2half2_rn(c, d);
    uint2 u;
    u.x = *reinterpret_cast<unsigned*>(&lo);
    u.y = *reinterpret_cast<unsigned*>(&hi);
    return u;
}

__device__ __forceinline__ float4 unpack4(uint2 u) {
    __half2 lo = *reinterpret_cast<__half2*>(&u.x);
    __half2 hi = *reinterpret_cast<__half2*>(&u.y);
    float2 a = __half22float2(lo);
    float2 c = __half22float2(hi);
    return make_float4(a.x, a.y, c.x, c.y);
}

// Convert feat fp32 -> fp16 cache; also zero g_cnt and build transposed fp16 W.
__global__ void __launch_bounds__(256) convert_kernel(
    const float* __restrict__ feat, const float* __restrict__ W)
{
    const int i = blockIdx.x * blockDim.x + threadIdx.x;
    if (i < N_ETYPES * N_NODES) g_cnt[i] = 0;
    if (i < D_OUT * D_IN) {
        const int j = i >> 7, k = i & 127;          // Wt16[j][k] = W[k][j]
        g_Wt16[i] = __float2half(W[k * D_OUT + j]);
    }
    if (i >= N_NODES * (D_IN / 4)) return;
    const float4 v = reinterpret_cast<const float4*>(feat)[i];
    g_feat16[i] = pack4(v.x, v.y, v.z, v.w);
}

// Pass 1: bin edges by (etype, dst). 4 edges per thread -> 4 independent chains.
__global__ void __launch_bounds__(256) bin_kernel(const int* __restrict__ edge_index)
{
    const int t = blockIdx.x * blockDim.x + threadIdx.x;
    if (t >= N_ETYPES * (E_PER_ETYPE / 4)) return;
    const int e    = t / (E_PER_ETYPE / 4);
    const int idx4 = (t - e * (E_PER_ETYPE / 4)) * 4;

    const int* base = edge_index + (size_t)e * 2 * E_PER_ETYPE;
    const int4 s = *reinterpret_cast<const int4*>(base + idx4);
    const int4 d = *reinterpret_cast<const int4*>(base + E_PER_ETYPE + idx4);

    const int s0 = atomicAdd(&g_cnt[e * N_NODES + d.x], 1);
    const int s1 = atomicAdd(&g_cnt[e * N_NODES + d.y], 1);
    const int s2 = atomicAdd(&g_cnt[e * N_NODES + d.z], 1);
    const int s3 = atomicAdd(&g_cnt[e * N_NODES + d.w], 1);

    if (s0 < CAP) g_bins[((size_t)e * N_NODES + d.x) * CAP + s0] = s.x;
    if (s1 < CAP) g_bins[((size_t)e * N_NODES + d.y) * CAP + s1] = s.y;
    if (s2 < CAP) g_bins[((size_t)e * N_NODES + d.z) * CAP + s2] = s.z;
    if (s3 < CAP) g_bins[((size_t)e * N_NODES + d.w) * CAP + s3] = s.w;
}

// Pass 2: pull gather-mean (fp16 payload, fp32 accum) + tanh + residual(fp32)
// + tanh -> g_h16. One warp per node; 2 independent gather chains. (R6 version)
__global__ void __launch_bounds__(256) gather_kernel(const float* __restrict__ feat)
{
    const int gw   = (blockIdx.x * blockDim.x + threadIdx.x) >> 5;
    const int lane = threadIdx.x & 31;
    if (gw >= N_NODES) return;
    const int n = gw;

    const float4 f = reinterpret_cast<const float4*>(feat)[(size_t)n * (D_IN / 4) + lane];
    float h0 = f.x, h1 = f.y, h2 = f.z, h3 = f.w;

    #pragma unroll
    for (int e = 0; e < N_ETYPES; e++) {
        const int c = g_cnt[e * N_NODES + n];
        const int* bin = g_bins + ((size_t)e * N_NODES + n) * CAP;
        float4 sa = make_float4(0.f, 0.f, 0.f, 0.f);
        float4 sb = make_float4(0.f, 0.f, 0.f, 0.f);
        int i = 0;
        for (; i + 2 <= c; i += 2) {
            const int2 p = *reinterpret_cast<const int2*>(bin + i);
            const float4 va = unpack4(__ldg(&g_feat16[(size_t)p.x * (D_IN / 4) + lane]));
            const float4 vb = unpack4(__ldg(&g_feat16[(size_t)p.y * (D_IN / 4) + lane]));
            sa.x += va.x; sa.y += va.y; sa.z += va.z; sa.w += va.w;
            sb.x += vb.x; sb.y += vb.y; sb.z += vb.z; sb.w += vb.w;
        }
        if (i < c) {
            const float4 va = unpack4(__ldg(&g_feat16[(size_t)bin[i] * (D_IN / 4) + lane]));
            sa.x += va.x; sa.y += va.y; sa.z += va.z; sa.w += va.w;
        }
        const float inv = 1.0f / fmaxf((float)c, 1.0f);
        h0 += P_ETYPE * tanh_fast((sa.x + sb.x) * inv);
        h1 += P_ETYPE * tanh_fast((sa.y + sb.y) * inv);
        h2 += P_ETYPE * tanh_fast((sa.z + sb.z) * inv);
        h3 += P_ETYPE * tanh_fast((sa.w + sb.w) * inv);
    }

    g_h16[(size_t)n * (D_IN / 4) + lane] =
        pack4(tanh_fast(h0), tanh_fast(h1), tanh_fast(h2), tanh_fast(h3));
}

// Pass 3: out = h @ W + b via HMMA (mma.sync m16n8k16, fp16 in / fp32 accum).
// Block = 256 threads / 128 nodes; warp computes 16 rows x 64 cols.
// A fragments straight from global h16 (L2-resident); B (Wt16) staged in shared.
// Wt16[j][k] is exactly the .col B operand (n-major, k contiguous).
__global__ void __launch_bounds__(256) gemm_hmma_kernel(
    const float* __restrict__ bias, float* __restrict__ out)
{
    __shared__ __align__(16) __half sW[D_OUT * D_IN];   // 16 KB

    const int tid = threadIdx.x;
    {
        const uint4* gw  = reinterpret_cast<const uint4*>(g_Wt16);
        uint4*       sw4 = reinterpret_cast<uint4*>(sW);
        #pragma unroll
        for (int i = tid; i < D_OUT * D_IN / 8; i += 256) sw4[i] = __ldg(&gw[i]);
    }
    __syncthreads();

    const int wid = tid >> 5, lid = tid & 31;
    const int g  = lid >> 2;        // group 0..7
    const int tg = lid & 3;         // thread-in-group 0..3

    const int row0 = blockIdx.x * 128 + wid * 16 + g;       // rows row0, row0+8
    const int r0 = min(row0,     N_NODES - 1);
    const int r1 = min(row0 + 8, N_NODES - 1);

    const uint32_t* h32 = reinterpret_cast<const uint32_t*>(g_h16);  // 64 b32 per row
    const uint32_t* w32 = reinterpret_cast<const uint32_t*>(sW);     // sW[n*64 + kb] b32

    float acc[8][4];
    #pragma unroll
    for (int nt = 0; nt < 8; nt++)
        #pragma unroll
        for (int c = 0; c < 4; c++) acc[nt][c] = 0.f;

    #pragma unroll
    for (int ks = 0; ks < 8; ks++) {
        // A frag (m16k16): a0=A[g][2tg..], a1=A[g+8][2tg..], a2=A[g][2tg+8..], a3=A[g+8][2tg+8..]
        const uint32_t a0 = __ldg(&h32[(size_t)r0 * 64 + ks * 8 + tg]);
        const uint32_t a1 = __ldg(&h32[(size_t)r1 * 64 + ks * 8 + tg]);
        const uint32_t a2 = __ldg(&h32[(size_t)r0 * 64 + ks * 8 + tg + 4]);
        const uint32_t a3 = __ldg(&h32[(size_t)r1 * 64 + ks * 8 + tg + 4]);
        #pragma unroll
        for (int nt = 0; nt < 8; nt++) {
            const int n = nt * 8 + g;
            // B frag (.col, k16 x n8): b0={B[2tg][n],B[2tg+1][n]}, b1 at k+8
            const uint32_t b0 = w32[n * 64 + ks * 8 + tg];
            const uint32_t b1 = w32[n * 64 + ks * 8 + tg + 4];
            asm volatile(
                "mma.sync.aligned.m16n8k16.row.col.f32.f16.f16.f32 "
                "{%0,%1,%2,%3}, {%4,%5,%6,%7}, {%8,%9}, {%0,%1,%2,%3};"
                : "+f"(acc[nt][0]), "+f"(acc[nt][1]), "+f"(acc[nt][2]), "+f"(acc[nt][3])
                : "r"(a0), "r"(a1), "r"(a2), "r"(a3), "r"(b0), "r"(b1));
        }
    }

    // D frag: c0=D[g][2tg], c1=D[g][2tg+1], c2=D[g+8][2tg], c3=D[g+8][2tg+1]
    const bool v0 = (row0     < N_NODES);
    const bool v1 = (row0 + 8 < N_NODES);
    const float2* b2 = reinterpret_cast<const float2*>(bias);
    float2* o2 = reinterpret_cast<float2*>(out);
    #pragma unroll
    for (int nt = 0; nt < 8; nt++) {
        const int col = nt * 8 + tg * 2;
        const float2 bb = __ldg(&b2[col >> 1]);
        if (v0) o2[((size_t)row0 * D_OUT + col) >> 1] =
                    make_float2(acc[nt][0] + bb.x, acc[nt][1] + bb.y);
        if (v1) o2[((size_t)(row0 + 8) * D_OUT + col) >> 1] =
                    make_float2(acc[nt][2] + bb.x, acc[nt][3] + bb.y);
    }
}

extern "C" void kernel_launch(void* const* d_in, const int* in_sizes, int n_in,
                              void* d_out, int out_size)
{
    // Identify inputs by unique element counts (robust to metadata ordering).
    const float* feat = nullptr;
    const float* W    = nullptr;
    const float* b    = nullptr;
    const int*   ei   = nullptr;
    for (int i = 0; i < n_in; i++) {
        switch (in_sizes[i]) {
            case 6400000: feat = (const float*)d_in[i]; break;
            case 8192:    W    = (const float*)d_in[i]; break;
            case 64:      b    = (const float*)d_in[i]; break;
            case 3000000: ei   = (const int*)d_in[i];   break;
            default: break;
        }
    }
    float* out = (float*)d_out;

    convert_kernel<<<(N_NODES * (D_IN / 4) + 255) / 256, 256>>>(feat, W);

    const int groups = N_ETYPES * (E_PER_ETYPE / 4);
    bin_kernel<<<(groups + 255) / 256, 256>>>(ei);

    gather_kernel<<<(N_NODES + 7) / 8, 256>>>(feat);

    gemm_hmma_kernel<<<(N_NODES + 127) / 128, 256>>>(b, out);
}